// round 10
// baseline (speedup 1.0000x reference)
#include <cuda_runtime.h>
#include <cuda_fp16.h>
#include <math.h>

#define B_SIZE    8192
#define K_FEATS   32
#define FT_OUT    512
#define BUCKETS   8
#define FT_VOCAB  40960
#define FFT_VOCAB 640

// Combined table quantized to int8 (biased-by-128 bytes) + per-row scale.
// comb[i][f] = ft_w[i][f] + fft_w[i%640][f]  ~=  (byte - 128) * g_scale[i]
__device__ unsigned char g_comb8[FT_VOCAB * FT_OUT];
__device__ float         g_scale[FT_VOCAB];

__device__ __forceinline__ int dp4a_us(unsigned int a, int b, int c) {
    int d;
    asm("dp4a.u32.s32 %0, %1, %2, %3;" : "=r"(d) : "r"(a), "r"(b), "r"(c));
    return d;
}

// ---------------------------------------------------------------------------
// Pass 1: quantize combined table. Warp-per-row, register-resident, at the
// DRAM floor (~15 us). Unchanged from R7/R8.
// ---------------------------------------------------------------------------
__global__ __launch_bounds__(256)
void combine_q_kernel(const float4* __restrict__ ftw,
                      const float4* __restrict__ fftw) {
    const int warp = threadIdx.x >> 5;
    const int lane = threadIdx.x & 31;
    const int row  = blockIdx.x * 8 + warp;

    const float4* fa = ftw  + (size_t)row * 128;
    const float4* fb = fftw + (size_t)(row % FFT_VOCAB) * 128;

    float4 c[4];
    #pragma unroll
    for (int i = 0; i < 4; ++i) {
        float4 a = __ldcs(fa + i * 32 + lane);
        float4 b = __ldg(fb + i * 32 + lane);
        c[i].x = a.x + b.x; c[i].y = a.y + b.y;
        c[i].z = a.z + b.z; c[i].w = a.w + b.w;
    }

    float m = 0.f;
    #pragma unroll
    for (int i = 0; i < 4; ++i)
        m = fmaxf(m, fmaxf(fmaxf(fabsf(c[i].x), fabsf(c[i].y)),
                           fmaxf(fabsf(c[i].z), fabsf(c[i].w))));
    #pragma unroll
    for (int o = 16; o > 0; o >>= 1)
        m = fmaxf(m, __shfl_xor_sync(0xffffffffu, m, o));
    m = fmaxf(m, 1e-20f);

    const float inv = 127.0f / m;
    uchar4* dst = reinterpret_cast<uchar4*>(g_comb8) + (size_t)row * 128;
    #pragma unroll
    for (int i = 0; i < 4; ++i) {
        uchar4 pk;
        pk.x = (unsigned char)(__float2int_rn(c[i].x * inv) + 128);
        pk.y = (unsigned char)(__float2int_rn(c[i].y * inv) + 128);
        pk.z = (unsigned char)(__float2int_rn(c[i].z * inv) + 128);
        pk.w = (unsigned char)(__float2int_rn(c[i].w * inv) + 128);
        dst[i * 32 + lane] = pk;
    }
    if (lane == 0) g_scale[row] = m * (1.0f / 127.0f);
}

// ---------------------------------------------------------------------------
// Pass 2: one block per batch row, 128 threads.
//   side = t >> 6 (0: stm, warps 0-1; 1: nstm, warps 2-3)
//   within side: p = k-parity (warp granularity), f = 16-feature group
// Thread (side, p, f) gathers 16 B (LDG.128) = feats [16f,16f+16) for its
// 16 parity-p k-values: 16 LDG.128 + 8 LDS total (half of R8's count).
// Per chunk of 4 same-parity k: 4 LDG.128 + 32 PRMT (4x4 byte transposes)
// + 16 DP4A into 16 int accumulators. Parity halves merged exactly via a
// 4 KB shared buffer in the epilogue.
// ---------------------------------------------------------------------------
__global__ __launch_bounds__(128)
void nnue_kernel(const float*  __restrict__ values,
                 const int*    __restrict__ stm_idx,
                 const int*    __restrict__ nstm_idx,
                 const int*    __restrict__ buckets,
                 const float*  __restrict__ ft_b,
                 const float*  __restrict__ fft_b,
                 const float*  __restrict__ out_w,
                 const float*  __restrict__ out_b,
                 float*        __restrict__ out) {
    const int b = blockIdx.x;
    const int t = threadIdx.x;
    const int side = t >> 6;
    const int p    = (t >> 5) & 1;     // k parity (whole warp)
    const int f    = t & 31;           // 16-feature group

    __shared__ int   offsD[2][2][16];  // [side][parity][j]  (k = 2j+p)
    __shared__ __align__(4) unsigned char sVD[2][2][16];
    __shared__ float sSq[2];
    __shared__ int   sSumV[2];
    __shared__ int   mrg[2][16][32];   // parity-1 partials: [side][i][f]
    __shared__ float red[2];

    // ---- prologue: warps 0 (stm) and 2 (nstm) build offsets + quantized V
    {
        const int wid  = t >> 5;
        const int lane = t & 31;
        if ((wid & 1) == 0) {
            const int sd = wid >> 1;
            const int* idxp = sd ? nstm_idx : stm_idx;
            const int idx = idxp[b * K_FEATS + lane];
            const int off = idx * FT_OUT;
            float vs = values[b * K_FEATS + lane] * g_scale[idx];

            float m = fabsf(vs);
            #pragma unroll
            for (int o = 16; o > 0; o >>= 1)
                m = fmaxf(m, __shfl_xor_sync(0xffffffffu, m, o));
            float Sq = fmaxf(m, 1e-30f) * (1.0f / 127.0f);

            int V = __float2int_rn(vs / Sq);          // in [-127,127]
            offsD[sd][lane & 1][lane >> 1] = off;
            sVD[sd][lane & 1][lane >> 1] = (unsigned char)(V & 0xff);

            int sv = V;
            #pragma unroll
            for (int o = 16; o > 0; o >>= 1)
                sv += __shfl_xor_sync(0xffffffffu, sv, o);
            if (lane == 0) { sSq[sd] = Sq; sSumV[sd] = sv; }
        }
    }
    __syncthreads();

    const char* base = reinterpret_cast<const char*>(g_comb8) + f * 16;
    const int*  offp = offsD[side][p];
    const int*  vpk  = reinterpret_cast<const int*>(sVD[side][p]);

    int acc[16];
    #pragma unroll
    for (int i = 0; i < 16; ++i) acc[i] = 0;

    #pragma unroll
    for (int c = 0; c < 4; ++c) {                // 4 chunks of 4 same-parity k
        int4 o4 = *reinterpret_cast<const int4*>(offp + c * 4);
        int  Vp = vpk[c];
        uint4 u0 = *reinterpret_cast<const uint4*>(base + o4.x);
        uint4 u1 = *reinterpret_cast<const uint4*>(base + o4.y);
        uint4 u2 = *reinterpret_cast<const uint4*>(base + o4.z);
        uint4 u3 = *reinterpret_cast<const uint4*>(base + o4.w);

        const unsigned int* w0 = reinterpret_cast<const unsigned int*>(&u0);
        const unsigned int* w1 = reinterpret_cast<const unsigned int*>(&u1);
        const unsigned int* w2 = reinterpret_cast<const unsigned int*>(&u2);
        const unsigned int* w3 = reinterpret_cast<const unsigned int*>(&u3);

        #pragma unroll
        for (int g = 0; g < 4; ++g) {            // 4x4 byte transpose + dp4a
            unsigned ta = __byte_perm(w0[g], w1[g], 0x5140);
            unsigned tb = __byte_perm(w2[g], w3[g], 0x5140);
            unsigned tc = __byte_perm(w0[g], w1[g], 0x7362);
            unsigned td = __byte_perm(w2[g], w3[g], 0x7362);
            acc[4*g+0] = dp4a_us(__byte_perm(ta, tb, 0x5410), Vp, acc[4*g+0]);
            acc[4*g+1] = dp4a_us(__byte_perm(ta, tb, 0x7632), Vp, acc[4*g+1]);
            acc[4*g+2] = dp4a_us(__byte_perm(tc, td, 0x5410), Vp, acc[4*g+2]);
            acc[4*g+3] = dp4a_us(__byte_perm(tc, td, 0x7632), Vp, acc[4*g+3]);
        }
    }

    // ---- parity merge (exact integer): parity-1 stores, parity-0 adds
    if (p == 1) {
        #pragma unroll
        for (int i = 0; i < 16; ++i) mrg[side][i][f] = acc[i];
    }
    __syncthreads();

    float local = 0.f;
    if (p == 0) {
        const float Sq   = sSq[side];
        const int   corr = 128 * sSumV[side];

        // biases for features [16f, 16f+16)
        const float4* bb4 = reinterpret_cast<const float4*>(ft_b)  + f * 4;
        const float4* fb4 = reinterpret_cast<const float4*>(fft_b) + f * 4;
        const int bk = buckets[b];
        const float4* wrow = reinterpret_cast<const float4*>(
            out_w + bk * (2 * FT_OUT) + side * FT_OUT) + f * 4;

        #pragma unroll
        for (int q = 0; q < 4; ++q) {            // 4 feature quads
            float4 bq = bb4[q], fq = fb4[q], wq = wrow[q];
            float h0 = (float)(acc[4*q+0] + mrg[side][4*q+0][f] - corr) * Sq + bq.x + fq.x;
            float h1 = (float)(acc[4*q+1] + mrg[side][4*q+1][f] - corr) * Sq + bq.y + fq.y;
            float h2 = (float)(acc[4*q+2] + mrg[side][4*q+2][f] - corr) * Sq + bq.z + fq.z;
            float h3 = (float)(acc[4*q+3] + mrg[side][4*q+3][f] - corr) * Sq + bq.w + fq.w;
            h0 = fminf(fmaxf(h0, 0.f), 1.f);
            h1 = fminf(fmaxf(h1, 0.f), 1.f);
            h2 = fminf(fmaxf(h2, 0.f), 1.f);
            h3 = fminf(fmaxf(h3, 0.f), 1.f);
            local += h0 * wq.x + h1 * wq.y + h2 * wq.z + h3 * wq.w;
        }

        // warp reduce (warp 0 = side 0, warp 2 = side 1; full warps)
        #pragma unroll
        for (int o = 16; o > 0; o >>= 1)
            local += __shfl_down_sync(0xffffffffu, local, o);
        if (f == 0) red[side] = local;
    }
    __syncthreads();
    if (t == 0) {
        const int bk = buckets[b];
        float s = red[0] + red[1] + out_b[bk];
        out[b] = 1.0f / (1.0f + expf(-s));
    }
}

extern "C" void kernel_launch(void* const* d_in, const int* in_sizes, int n_in,
                              void* d_out, int out_size) {
    const float* values   = (const float*)d_in[0];
    const int*   stm_idx  = (const int*)  d_in[1];
    const int*   nstm_idx = (const int*)  d_in[2];
    const int*   buckets  = (const int*)  d_in[3];
    const float* ft_w     = (const float*)d_in[4];
    const float* ft_b     = (const float*)d_in[5];
    const float* fft_w    = (const float*)d_in[6];
    const float* fft_b    = (const float*)d_in[7];
    const float* out_w    = (const float*)d_in[8];
    const float* out_b    = (const float*)d_in[9];
    float* out = (float*)d_out;

    (void)in_sizes; (void)n_in; (void)out_size;

    combine_q_kernel<<<FT_VOCAB / 8, 256>>>(
        reinterpret_cast<const float4*>(ft_w),
        reinterpret_cast<const float4*>(fft_w));

    nnue_kernel<<<B_SIZE, 128>>>(values, stm_idx, nstm_idx, buckets,
                                 ft_b, fft_b, out_w, out_b, out);
}

// round 11
// speedup vs baseline: 1.1918x; 1.1918x over previous
#include <cuda_runtime.h>
#include <cuda_fp16.h>
#include <math.h>

#define B_SIZE    8192
#define K_FEATS   32
#define FT_OUT    512
#define BUCKETS   8
#define FT_VOCAB  40960
#define FFT_VOCAB 640

// Combined table quantized to int8 (biased-by-128 bytes) + per-row scale.
// comb[i][f] = ft_w[i][f] + fft_w[i%640][f]  ~=  (byte - 128) * g_scale[i]
__device__ unsigned char g_comb8[FT_VOCAB * FT_OUT];
__device__ float         g_scale[FT_VOCAB];

__device__ __forceinline__ int dp4a_us(unsigned int a, int b, int c) {
    int d;
    asm("dp4a.u32.s32 %0, %1, %2, %3;" : "=r"(d) : "r"(a), "r"(b), "r"(c));
    return d;
}

// ---------------------------------------------------------------------------
// Pass 1: quantize combined table. Warp-per-row, register-resident, at the
// DRAM floor (~15 us). Unchanged from R7/R8.
// ---------------------------------------------------------------------------
__global__ __launch_bounds__(256)
void combine_q_kernel(const float4* __restrict__ ftw,
                      const float4* __restrict__ fftw) {
    const int warp = threadIdx.x >> 5;
    const int lane = threadIdx.x & 31;
    const int row  = blockIdx.x * 8 + warp;

    const float4* fa = ftw  + (size_t)row * 128;
    const float4* fb = fftw + (size_t)(row % FFT_VOCAB) * 128;

    float4 c[4];
    #pragma unroll
    for (int i = 0; i < 4; ++i) {
        float4 a = __ldcs(fa + i * 32 + lane);
        float4 b = __ldg(fb + i * 32 + lane);
        c[i].x = a.x + b.x; c[i].y = a.y + b.y;
        c[i].z = a.z + b.z; c[i].w = a.w + b.w;
    }

    float m = 0.f;
    #pragma unroll
    for (int i = 0; i < 4; ++i)
        m = fmaxf(m, fmaxf(fmaxf(fabsf(c[i].x), fabsf(c[i].y)),
                           fmaxf(fabsf(c[i].z), fabsf(c[i].w))));
    #pragma unroll
    for (int o = 16; o > 0; o >>= 1)
        m = fmaxf(m, __shfl_xor_sync(0xffffffffu, m, o));
    m = fmaxf(m, 1e-20f);

    const float inv = 127.0f / m;
    uchar4* dst = reinterpret_cast<uchar4*>(g_comb8) + (size_t)row * 128;
    #pragma unroll
    for (int i = 0; i < 4; ++i) {
        uchar4 pk;
        pk.x = (unsigned char)(__float2int_rn(c[i].x * inv) + 128);
        pk.y = (unsigned char)(__float2int_rn(c[i].y * inv) + 128);
        pk.z = (unsigned char)(__float2int_rn(c[i].z * inv) + 128);
        pk.w = (unsigned char)(__float2int_rn(c[i].w * inv) + 128);
        dst[i * 32 + lane] = pk;
    }
    if (lane == 0) g_scale[row] = m * (1.0f / 127.0f);
}

// ---------------------------------------------------------------------------
// Pass 2: one block per batch row, 128 threads (R8 structure).
//   warps 0-1 (t < 64):  stm half,  thread owns feats [8*col, 8*col+8)
//   warps 2-3 (t >= 64): nstm half
// Per-k weights vs_k = value_k * row_scale_k quantized to int8 V_k with one
// per-(row,side) scale Sq. Hot loop: 8 chunks of 4 k, each chunk =
// 4 LDG.64 + 16 PRMT (4x4 byte transpose) + 8 DP4A, with an explicit
// 2-stage software pipeline: chunk c+1's offsets + gathers are issued
// before chunk c's decode, keeping 4-8 loads continuously in flight.
// ---------------------------------------------------------------------------
__global__ __launch_bounds__(128)
void nnue_kernel(const float*  __restrict__ values,
                 const int*    __restrict__ stm_idx,
                 const int*    __restrict__ nstm_idx,
                 const int*    __restrict__ buckets,
                 const float*  __restrict__ ft_b,
                 const float*  __restrict__ fft_b,
                 const float*  __restrict__ out_w,
                 const float*  __restrict__ out_b,
                 float*        __restrict__ out) {
    const int b = blockIdx.x;
    const int t = threadIdx.x;
    const int half_sel = t >> 6;
    const int col      = t & 63;

    __shared__ int           offs[2][K_FEATS];
    __shared__ __align__(4) unsigned char sV[2][K_FEATS];
    __shared__ float sSq[2];
    __shared__ int   sSumV[2];
    __shared__ float red[4];

    {
        const int wid  = t >> 5;           // warp 0 -> stm, warp 2 -> nstm
        const int lane = t & 31;
        if ((wid & 1) == 0) {
            const int side = wid >> 1;
            const int* idxp = side ? nstm_idx : stm_idx;
            const int idx = idxp[b * K_FEATS + lane];
            offs[side][lane] = idx * FT_OUT;
            float vs = values[b * K_FEATS + lane] * g_scale[idx];

            // warp absmax -> per-side scale
            float m = fabsf(vs);
            #pragma unroll
            for (int o = 16; o > 0; o >>= 1)
                m = fmaxf(m, __shfl_xor_sync(0xffffffffu, m, o));
            m = fmaxf(m, 1e-30f);
            float Sq  = m * (1.0f / 127.0f);
            float inv = 127.0f / m;

            int V = __float2int_rn(vs * inv);         // in [-127,127]
            sV[side][lane] = (unsigned char)(V & 0xff);

            int sv = V;
            #pragma unroll
            for (int o = 16; o > 0; o >>= 1)
                sv += __shfl_xor_sync(0xffffffffu, sv, o);
            if (lane == 0) { sSq[side] = Sq; sSumV[side] = sv; }
        }
    }
    __syncthreads();

    const char* base = reinterpret_cast<const char*>(g_comb8) + col * 8;
    const int*  offp = offs[half_sel];
    const int*  vpk  = reinterpret_cast<const int*>(sV[half_sel]);

    int acc[8];
    #pragma unroll
    for (int f = 0; f < 8; ++f) acc[f] = 0;

    // ---- software-pipelined gather loop: prefetch chunk c+1 while
    //      decoding chunk c. Buffers alternate via unroll renaming.
    int4  o4 = *reinterpret_cast<const int4*>(offp);
    uint2 u0 = *reinterpret_cast<const uint2*>(base + o4.x);
    uint2 u1 = *reinterpret_cast<const uint2*>(base + o4.y);
    uint2 u2 = *reinterpret_cast<const uint2*>(base + o4.z);
    uint2 u3 = *reinterpret_cast<const uint2*>(base + o4.w);

    #pragma unroll
    for (int c = 0; c < 8; ++c) {
        // issue next chunk's loads first (independent of current decode)
        uint2 n0, n1, n2, n3;
        if (c < 7) {
            int4 o4n = *reinterpret_cast<const int4*>(offp + (c + 1) * 4);
            n0 = *reinterpret_cast<const uint2*>(base + o4n.x);
            n1 = *reinterpret_cast<const uint2*>(base + o4n.y);
            n2 = *reinterpret_cast<const uint2*>(base + o4n.z);
            n3 = *reinterpret_cast<const uint2*>(base + o4n.w);
        }

        const int Vp = vpk[c];

        // byte-transpose: r_f = {b_f(k0), b_f(k1), b_f(k2), b_f(k3)}
        unsigned ta = __byte_perm(u0.x, u1.x, 0x5140);
        unsigned tb = __byte_perm(u2.x, u3.x, 0x5140);
        unsigned tc = __byte_perm(u0.x, u1.x, 0x7362);
        unsigned td = __byte_perm(u2.x, u3.x, 0x7362);
        acc[0] = dp4a_us(__byte_perm(ta, tb, 0x5410), Vp, acc[0]);
        acc[1] = dp4a_us(__byte_perm(ta, tb, 0x7632), Vp, acc[1]);
        acc[2] = dp4a_us(__byte_perm(tc, td, 0x5410), Vp, acc[2]);
        acc[3] = dp4a_us(__byte_perm(tc, td, 0x7632), Vp, acc[3]);

        ta = __byte_perm(u0.y, u1.y, 0x5140);
        tb = __byte_perm(u2.y, u3.y, 0x5140);
        tc = __byte_perm(u0.y, u1.y, 0x7362);
        td = __byte_perm(u2.y, u3.y, 0x7362);
        acc[4] = dp4a_us(__byte_perm(ta, tb, 0x5410), Vp, acc[4]);
        acc[5] = dp4a_us(__byte_perm(ta, tb, 0x7632), Vp, acc[5]);
        acc[6] = dp4a_us(__byte_perm(tc, td, 0x5410), Vp, acc[6]);
        acc[7] = dp4a_us(__byte_perm(tc, td, 0x7632), Vp, acc[7]);

        if (c < 7) { u0 = n0; u1 = n1; u2 = n2; u3 = n3; }
    }

    // Undo +128 byte bias exactly, scale, add biases, clip.
    const float Sq   = sSq[half_sel];
    const int   corr = 128 * sSumV[half_sel];

    const float4* bb4 = reinterpret_cast<const float4*>(ft_b)  + col * 2;
    const float4* fb4 = reinterpret_cast<const float4*>(fft_b) + col * 2;
    float4 b0 = bb4[0], b1 = bb4[1], f0 = fb4[0], f1 = fb4[1];
    float bias[8] = { b0.x + f0.x, b0.y + f0.y, b0.z + f0.z, b0.w + f0.w,
                      b1.x + f1.x, b1.y + f1.y, b1.z + f1.z, b1.w + f1.w };

    float h[8];
    #pragma unroll
    for (int f = 0; f < 8; ++f) {
        h[f] = (float)(acc[f] - corr) * Sq + bias[f];
        h[f] = fminf(fmaxf(h[f], 0.f), 1.f);
    }

    // dot with the selected bucket row of out_w [BUCKETS, 2*FT_OUT]
    const int bk = buckets[b];
    const float4* wrow = reinterpret_cast<const float4*>(
        out_w + bk * (2 * FT_OUT) + half_sel * FT_OUT) + col * 2;
    float4 w0 = wrow[0], w1 = wrow[1];

    float local = h[0] * w0.x + h[1] * w0.y + h[2] * w0.z + h[3] * w0.w
                + h[4] * w1.x + h[5] * w1.y + h[6] * w1.z + h[7] * w1.w;

    #pragma unroll
    for (int o = 16; o > 0; o >>= 1)
        local += __shfl_down_sync(0xffffffffu, local, o);
    if ((t & 31) == 0) red[t >> 5] = local;
    __syncthreads();
    if (t == 0) {
        float s = red[0] + red[1] + red[2] + red[3] + out_b[bk];
        out[b] = 1.0f / (1.0f + expf(-s));
    }
}

extern "C" void kernel_launch(void* const* d_in, const int* in_sizes, int n_in,
                              void* d_out, int out_size) {
    const float* values   = (const float*)d_in[0];
    const int*   stm_idx  = (const int*)  d_in[1];
    const int*   nstm_idx = (const int*)  d_in[2];
    const int*   buckets  = (const int*)  d_in[3];
    const float* ft_w     = (const float*)d_in[4];
    const float* ft_b     = (const float*)d_in[5];
    const float* fft_w    = (const float*)d_in[6];
    const float* fft_b    = (const float*)d_in[7];
    const float* out_w    = (const float*)d_in[8];
    const float* out_b    = (const float*)d_in[9];
    float* out = (float*)d_out;

    (void)in_sizes; (void)n_in; (void)out_size;

    combine_q_kernel<<<FT_VOCAB / 8, 256>>>(
        reinterpret_cast<const float4*>(ft_w),
        reinterpret_cast<const float4*>(fft_w));

    nnue_kernel<<<B_SIZE, 128>>>(values, stm_idx, nstm_idx, buckets,
                                 ft_b, fft_b, out_w, out_b, out);
}